// round 12
// baseline (speedup 1.0000x reference)
#include <cuda_runtime.h>
#include <cuda_bf16.h>
#include <cstdint>

#define Bd   64
#define Dd   512
#define Td   50
#define Sd   400
#define KTOP 50
#define NEGV (-1e6f)
#define NBLK 148
#define TPB  512
#define NT   (NBLK*TPB)
#define NUNIT (NBLK*2)
#define HSZ  (Bd*Dd)

// ---- output layout ----
#define OFF_G     0
#define SZ_G      (Td*Bd*256)
#define OFF_H     (OFF_G + SZ_G)
#define SZ_H      (2*Bd*Dd)
#define OFF_ATTN  (OFF_H + SZ_H)
#define SZ_ATTN   (Td*Bd*Sd)
#define OFF_TATTN (OFF_ATTN + SZ_ATTN)
#define SZ_TATTN  (Td*Bd*KTOP)
#define OFF_MIX   (OFF_TATTN + SZ_TATTN)
#define OFF_GATE  (OFF_MIX + Bd*Dd)

// ---- scratch ----
__device__ float g_pre [Sd*Bd*Dd];
__device__ float g_tpre[KTOP*Bd*Dd];
__device__ float g_emb [Td*Bd*Dd];
__device__ float g_embIH[Td*Bd*1536];
__device__ float g_embRO[Td*Bd*512];
__device__ float g_Wt_ih0[1024*1536];
__device__ float g_Wt_hh0[512*1536];
__device__ float g_Wt_ih1[512*1536];
__device__ float g_Wt_hh1[512*1536];
__device__ float g_Wt_ro [1536*512];
__device__ float g_Wt_q  [512*512];
__device__ float g_Wt_tq [512*512];
__device__ float g_Wt_pre[512*512];
__device__ float g_Wt_tpre[512*512];
__device__ float g_h0[HSZ];
__device__ float g_h1[HSZ];
__device__ float g_mix[HSZ];
__device__ float g_xr[Bd*1024];
__device__ float g_gate[Bd];
__device__ float g_e[Bd*(Sd+KTOP)];
__device__ float g_pIH0[8*Bd*1536];
__device__ float g_pHH0[8*Bd*1536];
__device__ float g_pIH1[16*Bd*1536];
__device__ float g_pHH1[16*Bd*1536];
__device__ float g_pQ  [16*Bd*512];
__device__ float g_pTQ [16*Bd*512];
__device__ float g_pRO [16*Bd*512];
// barrier state
__device__ unsigned g_cnt2;
__device__ volatile unsigned g_phase;
__device__ unsigned g_bc[64*8];

__device__ __forceinline__ float tanh_fast(float x){
    float y; asm("tanh.approx.f32 %0, %1;" : "=f"(y) : "f"(x)); return y;
}
__device__ __forceinline__ float sigm(float x){ return 1.f/(1.f+__expf(-x)); }

__device__ __forceinline__ float tanh_poly(float x){
    float f = x*x;
    float p = fmaf(f, 0.02186949f, -0.05396825f);
    p = fmaf(f, p, 0.13333333f);
    p = fmaf(f, p, -0.33333333f);
    p = fmaf(f, p, 1.0f);
    return x*p;
}

// 256-thread unit barrier (warps 0-7 -> id 1, warps 8-15 -> id 2)
__device__ __forceinline__ void ubar(int u){
    asm volatile("bar.sync %0, 256;" :: "r"(u+1) : "memory");
}

// grid barrier, 148 arrivals; lp RELATIVE (replay-safe)
__device__ __forceinline__ void gsync(unsigned &lp){
    __syncthreads();
    lp++;
    if (threadIdx.x == 0){
        __threadfence();
        if (atomicAdd(&g_cnt2, 1u) == NBLK-1u){
            g_cnt2 = 0;
            __threadfence();
            g_phase = lp;
        } else {
            while (g_phase < lp) { __nanosleep(32); }
        }
        __threadfence();
    }
    __syncthreads();
}

__device__ __forceinline__ float wsum32(float v){
    #pragma unroll
    for (int o = 16; o; o >>= 1) v += __shfl_xor_sync(0xffffffffu, v, o);
    return v;
}
__device__ __forceinline__ float wmax32(float v){
    #pragma unroll
    for (int o = 16; o; o >>= 1) v = fmaxf(v, __shfl_xor_sync(0xffffffffu, v, o));
    return v;
}

// ---- tiled GEMM job on a 256-thread unit, double-buffered smem
__device__ __forceinline__ void gemm_job(
    const float* __restrict__ X, int ldx,
    const float* __restrict__ Wt, int N,
    float* __restrict__ part, int n0, int k0, int kc,
    float (*as)[72], float (*bs)[72], int utid, int u)
{
    int lr  = utid >> 2, lc4 = (utid & 3) * 4;
    int kkb = utid >> 4, nnb = (utid & 15) * 4;
    int mi0 = (utid >> 4) * 4, ni0 = (utid & 15) * 4;
    float acc[4][4] = {};
    const float* xsrc = X + (size_t)lr*ldx + k0 + lc4;
    const float* wsrc = Wt + (size_t)(k0+kkb)*N + n0 + nnb;
    int nch = kc >> 4;
    float4 xv = *(const float4*)xsrc;
    float4 wv = *(const float4*)wsrc;
    for (int c = 0; c < nch; c++){
        int buf = (c & 1) << 4;
        as[buf+lc4+0][lr] = xv.x; as[buf+lc4+1][lr] = xv.y;
        as[buf+lc4+2][lr] = xv.z; as[buf+lc4+3][lr] = xv.w;
        *(float4*)&bs[buf+kkb][nnb] = wv;
        ubar(u);
        if (c+1 < nch){
            xv = *(const float4*)(xsrc + (c+1)*16);
            wv = *(const float4*)(wsrc + (size_t)(c+1)*16*N);
        }
        #pragma unroll
        for (int kk = 0; kk < 16; kk++){
            float4 av = *(const float4*)&as[buf+kk][mi0];
            float4 bv = *(const float4*)&bs[buf+kk][ni0];
            float a_[4] = {av.x, av.y, av.z, av.w};
            float b_[4] = {bv.x, bv.y, bv.z, bv.w};
            #pragma unroll
            for (int i = 0; i < 4; i++)
                #pragma unroll
                for (int j = 0; j < 4; j++)
                    acc[i][j] = fmaf(a_[i], b_[j], acc[i][j]);
        }
    }
    ubar(u);
    #pragma unroll
    for (int i = 0; i < 4; i++){
        *(float4*)(part + (size_t)(mi0+i)*N + n0 + ni0) =
            make_float4(acc[i][0], acc[i][1], acc[i][2], acc[i][3]);
    }
}

struct GemG {
    const float* X; int ldx;
    const float* Wt; int N;
    float* part;
    int kc; int nnt; int njobs;
};

__device__ __forceinline__ void run_gems(const GemG* gs, int ng,
                                         int unit, int utid, int u,
                                         float (*as)[72], float (*bs)[72]){
    int tot = 0;
    for (int g = 0; g < ng; g++) tot += gs[g].njobs;
    for (int j = unit; j < tot; j += NUNIT){
        int g = 0, base = 0;
        while (j >= base + gs[g].njobs){ base += gs[g].njobs; g++; }
        int local = j - base;
        int nt = local % gs[g].nnt;
        int ks = local / gs[g].nnt;
        gemm_job(gs[g].X, gs[g].ldx, gs[g].Wt, gs[g].N,
                 gs[g].part + (size_t)ks*Bd*gs[g].N,
                 nt*64, ks*gs[g].kc, gs[g].kc, as, bs, utid, u);
    }
}

// GRU epilogue over per-block contiguous chunk (all 148 SMs engaged)
__device__ __forceinline__ void gru_epi(
    const float* __restrict__ pIH, int nIH,
    const float* __restrict__ pHH, int nHH,
    const float* __restrict__ embp,
    const float* __restrict__ bih, const float* __restrict__ bhh,
    float* __restrict__ h)
{
    const int per = (HSZ + NBLK - 1)/NBLK;        // 222
    int i0 = blockIdx.x*per;
    int iend = i0 + per; if (iend > HSZ) iend = HSZ;
    for (int i = i0 + threadIdx.x; i < iend; i += TPB){
        int b = i >> 9, d = i & 511;
        float gir = bih[d], giz = bih[512+d], gin = bih[1024+d];
        if (embp){
            const float* e = embp + (size_t)b*1536;
            gir += e[d]; giz += e[512+d]; gin += e[1024+d];
        }
        for (int s = 0; s < nIH; s++){
            const float* p = pIH + (size_t)s*Bd*1536 + (size_t)b*1536;
            gir += p[d]; giz += p[512+d]; gin += p[1024+d];
        }
        float ghr = bhh[d], ghz = bhh[512+d], ghn = bhh[1024+d];
        for (int s = 0; s < nHH; s++){
            const float* p = pHH + (size_t)s*Bd*1536 + (size_t)b*1536;
            ghr += p[d]; ghz += p[512+d]; ghn += p[1024+d];
        }
        float r = sigm(gir + ghr);
        float z = sigm(giz + ghz);
        float n = tanhf(gin + r*ghn);
        h[i] = (1.f - z)*n + z*h[i];
    }
}

__global__ void __launch_bounds__(TPB, 1)
k_persist(const float* __restrict__ context, const float* __restrict__ smask,
          const float* __restrict__ tcontext, const float* __restrict__ tmask,
          const float* __restrict__ mix0,
          const float* __restrict__ b_ih0, const float* __restrict__ b_hh0,
          const float* __restrict__ b_ih1, const float* __restrict__ b_hh1,
          const float* __restrict__ attn_v, const float* __restrict__ tattn_v,
          const float* __restrict__ readout_b,
          const float* __restrict__ gate_W, const float* __restrict__ gate_b,
          float* __restrict__ out)
{
    __shared__ union {
        struct { float as[2][32][72]; float bs[2][32][72]; } g;   // gemm phases
        struct { float qsm[2][512]; float tqsm[2][512]; float sh[2][512]; } p;  // PDPE
    } smu;
    __shared__ __align__(16) float vsm[512], tvsm[512];
    const int blk = blockIdx.x;
    const int tid = threadIdx.x;
    const int u   = tid >> 8;              // unit 0/1 within block
    const int utid = tid & 255;
    const int uwarp = utid >> 5, lane = tid & 31;
    const int unit = blk*2 + u;            // 0..295
    const int gtid = blk*TPB + tid;
    unsigned lp = g_phase;                 // relative (replay-safe)
    // per-unit PDPE ids
    const int pb = unit >> 2, pq = unit & 3;
    unsigned bcbase = 0;
    if (unit < 256 && utid == 0) bcbase = g_bc[pb*8];

    for (int i = tid; i < 512; i += TPB){ vsm[i] = attn_v[i]; tvsm[i] = tattn_v[i]; }

    // P0: mix = mix0
    for (int i = gtid; i < HSZ; i += NT) g_mix[i] = mix0[i];
    gsync(lp);

    // P1: GRU0(0) gemms
    {
        GemG gs[2] = {
            { g_mix, 512, g_Wt_ih0 + (size_t)512*1536, 1536, g_pIH0, 64, 24, 192 },
            { g_h0,  512, g_Wt_hh0,                    1536, g_pHH0, 64, 24, 192 },
        };
        run_gems(gs, 2, unit, utid, u, smu.g.as[u], smu.g.bs[u]);
    }
    gsync(lp);

    for (int t = 0; t < Td; t++){
        // epiA: GRU0 epilogue -> h0
        gru_epi(g_pIH0, 8, g_pHH0, 8, g_embIH + (size_t)t*Bd*1536,
                b_ih0, b_hh0, g_h0);
        gsync(lp);

        // gemB: GRU1 gemms (768 jobs over 296 units)
        {
            GemG gs[2] = {
                { g_h0, 512, g_Wt_ih1, 1536, g_pIH1, 32, 24, 384 },
                { g_h1, 512, g_Wt_hh1, 1536, g_pHH1, 32, 24, 384 },
            };
            run_gems(gs, 2, unit, utid, u, smu.g.as[u], smu.g.bs[u]);
        }
        gsync(lp);

        // epiC: GRU1 epilogue -> h1
        gru_epi(g_pIH1, 16, g_pHH1, 16, nullptr, b_ih1, b_hh1, g_h1);
        gsync(lp);

        // gemD: q + tq gemms (256 jobs) + maxout(t-1)
        {
            GemG gs[2] = {
                { g_h1, 512, g_Wt_q,  512, g_pQ,  32, 8, 128 },
                { g_h1, 512, g_Wt_tq, 512, g_pTQ, 32, 8, 128 },
            };
            run_gems(gs, 2, unit, utid, u, smu.g.as[u], smu.g.bs[u]);
            if (t > 0){
                const float* embro = g_embRO + (size_t)(t-1)*Bd*512;
                const int per = (Bd*256 + NBLK - 1)/NBLK;      // 111
                int i0 = blk*per;
                int iend = i0 + per; if (iend > Bd*256) iend = Bd*256;
                for (int i = i0 + tid; i < iend; i += TPB){
                    int b = i >> 8, j = i & 255;
                    const float* e = embro + (size_t)b*512;
                    float r0 = readout_b[2*j]   + e[2*j];
                    float r1 = readout_b[2*j+1] + e[2*j+1];
                    #pragma unroll
                    for (int s = 0; s < 16; s++){
                        const float* p = g_pRO + (size_t)s*Bd*512 + (size_t)b*512;
                        r0 += p[2*j]; r1 += p[2*j+1];
                    }
                    out[OFF_G + (size_t)(t-1)*Bd*256 + i] = fmaxf(r0, r1);
                }
            }
        }
        gsync(lp);

        // PDPE: energies + per-b mini-barrier + softmax + weighted sums
        if (unit < 256){
            const int b = pb, q = pq;
            float* qsm  = smu.p.qsm[u];
            float* tqsm = smu.p.tqsm[u];
            float* sh   = smu.p.sh[u];
            // q/tq partial sums into smem
            for (int i = utid; i < 128; i += 256){
                float4 s1 = make_float4(0.f,0.f,0.f,0.f);
                float4 s2 = make_float4(0.f,0.f,0.f,0.f);
                #pragma unroll
                for (int s = 0; s < 16; s++){
                    float4 p1 = *(const float4*)&g_pQ [(size_t)s*HSZ + (size_t)b*512 + i*4];
                    float4 p2 = *(const float4*)&g_pTQ[(size_t)s*HSZ + (size_t)b*512 + i*4];
                    s1.x += p1.x; s1.y += p1.y; s1.z += p1.z; s1.w += p1.w;
                    s2.x += p2.x; s2.y += p2.y; s2.z += p2.z; s2.w += p2.w;
                }
                *(float4*)&qsm[i*4]  = s1;
                *(float4*)&tqsm[i*4] = s2;
            }
            ubar(u);
            if (q == 0 && uwarp == 0){
                const float4* h4 = (const float4*)(g_h1 + (size_t)b*512);
                const float4* w4 = (const float4*)gate_W;
                float p = 0.f;
                #pragma unroll
                for (int i = lane; i < 128; i += 32){
                    float4 h = h4[i], w = w4[i];
                    p += h.x*w.x + h.y*w.y + h.z*w.z + h.w*w.w;
                }
                p = wsum32(p);
                if (lane == 0){
                    float g = sigm(p + gate_b[0]);
                    g_gate[b] = g;
                    out[OFF_GATE + (size_t)t*Bd + b] = g;
                }
            }
            int qstart = (450*q) >> 2, qend = (450*(q+1)) >> 2;
            for (int i = qstart + uwarp; i < qend; i += 8){
                const float* prow; const float* qs; const float* vs;
                bool masked; int eidx;
                if (i < Sd){
                    prow = g_pre + ((size_t)i*Bd + b)*512;
                    qs = qsm; vs = vsm;
                    masked = smask[(size_t)b*Sd + i] > 0.5f;
                    eidx = b*(Sd+KTOP) + i;
                } else {
                    int jj = i - Sd;
                    prow = g_tpre + ((size_t)jj*Bd + b)*512;
                    qs = tqsm; vs = tvsm;
                    masked = tmask[(size_t)b*KTOP + jj] > 0.5f;
                    eidx = b*(Sd+KTOP) + i;
                }
                const float4* p4 = (const float4*)prow;
                float p = 0.f;
                #pragma unroll
                for (int i2 = lane; i2 < 128; i2 += 32){
                    float4 pp = p4[i2];
                    float4 qq = *(const float4*)&qs[i2*4];
                    float4 vx = *(const float4*)&vs[i2*4];
                    float x0 = pp.x+qq.x, x1 = pp.y+qq.y;
                    float x2 = pp.z+qq.z, x3 = pp.w+qq.w;
                    float mx = fmaxf(fmaxf(fabsf(x0),fabsf(x1)),
                                     fmaxf(fabsf(x2),fabsf(x3)));
                    if (__any_sync(0xffffffffu, mx > 0.55f)){
                        p += vx.x*tanh_fast(x0) + vx.y*tanh_fast(x1)
                           + vx.z*tanh_fast(x2) + vx.w*tanh_fast(x3);
                    } else {
                        p += vx.x*tanh_poly(x0) + vx.y*tanh_poly(x1)
                           + vx.z*tanh_poly(x2) + vx.w*tanh_poly(x3);
                    }
                }
                p = wsum32(p);
                if (lane == 0) g_e[eidx] = masked ? NEGV : p;
            }
            // ---- per-b mini-barrier (4 units) ----
            ubar(u);
            if (utid == 0){
                __threadfence();
                atomicAdd(&g_bc[b*8], 1u);
                unsigned target = bcbase + 4u*(unsigned)(t+1);
                while (*((volatile unsigned*)&g_bc[b*8]) < target) { __nanosleep(32); }
                __threadfence();
            }
            ubar(u);
            // ---- PE part (qsm reused for exp(e)) ----
            for (int j = utid; j < Sd+KTOP; j += 256) qsm[j] = g_e[(size_t)b*(Sd+KTOP) + j];
            ubar(u);
            float m = -1e30f;
            for (int j = utid; j < Sd; j += 256) m = fmaxf(m, qsm[j]);
            m = wmax32(m);
            if (lane == 0) sh[uwarp] = m;
            ubar(u);
            if (utid == 0){
                float mm = sh[0];
                for (int w = 1; w < 8; w++) mm = fmaxf(mm, sh[w]);
                sh[16] = mm;
            }
            ubar(u);
            float smax = sh[16];
            float ss = 0.f;
            for (int j = utid; j < Sd; j += 256){
                float ex = __expf(qsm[j] - smax); qsm[j] = ex; ss += ex;
            }
            ss = wsum32(ss);
            if (lane == 0) sh[uwarp] = ss;
            ubar(u);
            if (utid == 0){
                float s = 0.f;
                for (int w = 0; w < 8; w++) s += sh[w];
                sh[17] = 1.f/s;
            }
            ubar(u);
            float sinv = sh[17];
            if (uwarp == 0){
                float tm = -1e30f;
                for (int j = lane; j < KTOP; j += 32) tm = fmaxf(tm, qsm[Sd+j]);
                tm = wmax32(tm);
                float te = 0.f;
                for (int j = lane; j < KTOP; j += 32){
                    float ex = __expf(qsm[Sd+j] - tm); qsm[Sd+j] = ex; te += ex;
                }
                te = wsum32(te);
                if (lane == 0) sh[18] = 1.f/te;
            }
            ubar(u);
            float tinv = sh[18];
            if (q == 0){
                for (int j = utid; j < Sd; j += 256)
                    out[OFF_ATTN + (size_t)t*Bd*Sd + (size_t)b*Sd + j] = qsm[j]*sinv;
                if (utid < KTOP)
                    out[OFF_TATTN + (size_t)t*Bd*KTOP + (size_t)b*KTOP + utid] = qsm[Sd+utid]*tinv;
            }
            int dl = utid & 127, lh = utid >> 7;
            int d2 = q*128 + dl;
            const float* cb = context + (size_t)b*Dd + d2;
            float a0 = 0.f, a1 = 0.f;
            int l0 = lh*200;
            for (int l = l0; l < l0+200; l += 2){
                a0 += qsm[l]  *cb[(size_t)(l  )*HSZ];
                a1 += qsm[l+1]*cb[(size_t)(l+1)*HSZ];
            }
            tqsm[utid] = a0 + a1;
            const float* tb = tcontext + (size_t)b*Dd + d2;
            float t0 = 0.f;
            int tl0 = lh*25;
            for (int l = tl0; l < tl0+25; l++)
                t0 += qsm[Sd+l]*tb[(size_t)l*HSZ];
            sh[utid] = t0;
            ubar(u);
            if (utid < 128){
                float c  = (tqsm[utid] + tqsm[utid+128]) * sinv;
                float tc = (sh[utid]   + sh[utid+128])   * tinv;
                float g = g_gate[b];
                float mval = g*c + (1.f - g)*tc;
                g_xr[(size_t)b*1024 + d2]       = g_h1[(size_t)b*Dd + d2];
                g_xr[(size_t)b*1024 + 512 + d2] = mval;
                g_mix[(size_t)b*512 + d2] = mval;
                if (t == Td-1) out[OFF_MIX + (size_t)b*Dd + d2] = mval;
            }
        }
        gsync(lp);

        // gemF: readout + (t<Td-1: GRU0(t+1) gemms)
        if (t < Td-1){
            GemG gs[3] = {
                { g_xr, 1024, g_Wt_ro  + (size_t)512*512,   512, g_pRO,  64,  8, 128 },
                { g_mix, 512, g_Wt_ih0 + (size_t)512*1536, 1536, g_pIH0, 64, 24, 192 },
                { g_h0,  512, g_Wt_hh0,                    1536, g_pHH0, 64, 24, 192 },
            };
            run_gems(gs, 3, unit, utid, u, smu.g.as[u], smu.g.bs[u]);
        } else {
            GemG gs[1] = {
                { g_xr, 1024, g_Wt_ro + (size_t)512*512, 512, g_pRO, 64, 8, 128 },
            };
            run_gems(gs, 1, unit, utid, u, smu.g.as[u], smu.g.bs[u]);
        }
        gsync(lp);
    }

    // postlude: maxout(Td-1) + h finals
    {
        const float* embro = g_embRO + (size_t)(Td-1)*Bd*512;
        for (int i = gtid; i < Bd*256; i += NT){
            int b = i >> 8, j = i & 255;
            const float* e = embro + (size_t)b*512;
            float r0 = readout_b[2*j]   + e[2*j];
            float r1 = readout_b[2*j+1] + e[2*j+1];
            #pragma unroll
            for (int s = 0; s < 16; s++){
                const float* p = g_pRO + (size_t)s*Bd*512 + (size_t)b*512;
                r0 += p[2*j]; r1 += p[2*j+1];
            }
            out[OFF_G + (size_t)(Td-1)*Bd*256 + i] = fmaxf(r0, r1);
        }
    }
    for (int i = gtid; i < HSZ; i += NT){
        out[OFF_H + i]       = g_h0[i];
        out[OFF_H + HSZ + i] = g_h1[i];
    }
}

// ---------------- precompute kernels ----------------

__global__ void k_trans_all(const float* __restrict__ W_ih0, const float* __restrict__ W_hh0,
                            const float* __restrict__ W_ih1, const float* __restrict__ W_hh1,
                            const float* __restrict__ readout_W,
                            const float* __restrict__ attn_q_W, const float* __restrict__ tattn_q_W,
                            const float* __restrict__ attn_pre_W, const float* __restrict__ tattn_pre_W,
                            const int* __restrict__ tgt, const float* __restrict__ table){
    __shared__ float tile[32][33];
    int bid = blockIdx.x;
    int tid = threadIdx.x;
    if (bid >= 5632){
        int r0 = (bid - 5632) * 16;
        for (int e = tid; e < 16*512; e += 256){
            int row = r0 + (e >> 9), d = e & 511;
            int tok = tgt[row];
            g_emb[(size_t)row*512 + d] = table[(size_t)tok*512 + d];
        }
        return;
    }
    const float* src; float* dst; int R, C, t0;
    if      (bid < 1536){ src=W_ih0;       dst=g_Wt_ih0;  R=1536; C=1024; t0=0; }
    else if (bid < 2304){ src=W_hh0;       dst=g_Wt_hh0;  R=1536; C=512;  t0=1536; }
    else if (bid < 3072){ src=W_ih1;       dst=g_Wt_ih1;  R=1536; C=512;  t0=2304; }
    else if (bid < 3840){ src=W_hh1;       dst=g_Wt_hh1;  R=1536; C=512;  t0=3072; }
    else if (bid < 4608){ src=readout_W;   dst=g_Wt_ro;   R=512;  C=1536; t0=3840; }
    else if (bid < 4864){ src=attn_q_W;    dst=g_Wt_q;    R=512;  C=512;  t0=4608; }
    else if (bid < 5120){ src=tattn_q_W;   dst=g_Wt_tq;   R=512;  C=512;  t0=4864; }
    else if (bid < 5376){ src=attn_pre_W;  dst=g_Wt_pre;  R=512;  C=512;  t0=5120; }
    else                { src=tattn_pre_W; dst=g_Wt_tpre; R=512;  C=512;  t0=5376; }
    int lt = bid - t0;
    int ctiles = C >> 5;
    int tr = lt / ctiles, tc = lt % ctiles;
    int r0 = tr << 5, c0 = tc << 5;
    int ty = tid >> 5, tx = tid & 31;
    for (int rr = ty; rr < 32; rr += 8)
        tile[rr][tx] = src[(size_t)(r0+rr)*C + c0 + tx];
    __syncthreads();
    for (int rr = ty; rr < 32; rr += 8)
        dst[(size_t)(c0+rr)*R + r0 + tx] = tile[tx][rr];
}

__global__ void k_init(const float* __restrict__ hidden){
    int i = blockIdx.x*blockDim.x + threadIdx.x;
    if (i == 0){ g_cnt2 = 0; g_phase = 0; }
    if (i < 64*8) g_bc[i] = 0;
    if (i < HSZ){
        g_h0[i] = hidden[i];
        g_h1[i] = hidden[HSZ + i];
    }
}

__global__ void k_pre2(const float* __restrict__ context, const float* __restrict__ tcontext,
                       const float* __restrict__ attn_pre_b, const float* __restrict__ tattn_pre_b){
    int bid = blockIdx.x;
    const float *X, *Wt, *bias; float* C; int N, base;
    if      (bid < 800) { X=context;  Wt=g_Wt_pre;  bias=attn_pre_b;  C=g_pre;   N=512;  base=0; }
    else if (bid < 900) { X=tcontext; Wt=g_Wt_tpre; bias=tattn_pre_b; C=g_tpre;  N=512;  base=800; }
    else if (bid < 1200){ X=g_emb;    Wt=g_Wt_ih0;  bias=nullptr;     C=g_embIH; N=1536; base=900; }
    else                { X=g_emb;    Wt=g_Wt_ro;   bias=nullptr;     C=g_embRO; N=512;  base=1200; }
    int lb = bid - base;
    int ntiles = N >> 7;
    const int m0 = (lb / ntiles) * 128;
    const int n0 = (lb % ntiles) * 128;
    __shared__ __align__(16) float ash[16][132];
    __shared__ __align__(16) float bsh[16][136];
    int tid = threadIdx.x;
    int mi0 = (tid >> 4) * 8;
    int ni0 = (tid & 15) * 8;
    float acc[8][8] = {};
    int lr = tid >> 2, lc = (tid & 3) * 4;
    int kb = tid >> 5, nb4 = (tid & 31) * 4;
    for (int k0 = 0; k0 < 512; k0 += 16){
        #pragma unroll
        for (int h = 0; h < 2; h++){
            int row = lr + h*64;
            float4 xv = *(const float4*)(X + (size_t)(m0+row)*512 + k0 + lc);
            ash[lc+0][row] = xv.x; ash[lc+1][row] = xv.y;
            ash[lc+2][row] = xv.z; ash[lc+3][row] = xv.w;
        }
        #pragma unroll
        for (int h = 0; h < 2; h++){
            int kk = kb + h*8;
            *(float4*)&bsh[kk][nb4] = *(const float4*)(Wt + (size_t)(k0+kk)*N + n0 + nb4);
        }
        __syncthreads();
        #pragma unroll
        for (int kk = 0; kk < 16; kk++){
            float a_[8], b_[8];
            float4 a0 = *(const float4*)&ash[kk][mi0];
            float4 a1 = *(const float4*)&ash[kk][mi0+4];
            float4 b0 = *(const float4*)&bsh[kk][ni0];
            float4 b1 = *(const float4*)&bsh[kk][ni0+4];
            a_[0]=a0.x;a_[1]=a0.y;a_[2]=a0.z;a_[3]=a0.w;
            a_[4]=a1.x;a_[5]=a1.y;a_[6]=a1.z;a_[7]=a1.w;
            b_[0]=b0.x;b_[1]=b0.y;b_[2]=b0.z;b_[3]=b0.w;
            b_[4]=b1.x;b_[5]=b1.y;b_[6]=b1.z;b_[7]=b1.w;
            #pragma unroll
            for (int i = 0; i < 8; i++)
                #pragma unroll
                for (int j = 0; j < 8; j++)
                    acc[i][j] = fmaf(a_[i], b_[j], acc[i][j]);
        }
        __syncthreads();
    }
    #pragma unroll
    for (int i = 0; i < 8; i++){
        float* cp = C + (size_t)(m0+mi0+i)*N + n0 + ni0;
        #pragma unroll
        for (int j = 0; j < 8; j++)
            cp[j] = acc[i][j] + (bias ? bias[n0+ni0+j] : 0.f);
    }
}

// ---------------- host ----------------

extern "C" void kernel_launch(void* const* d_in, const int* in_sizes, int n_in,
                              void* d_out, int out_size){
    const int*   tgt        = (const int*)  d_in[0];
    const float* hidden     = (const float*)d_in[1];
    const float* context    = (const float*)d_in[2];
    const float* smask      = (const float*)d_in[3];
    const float* tcontext   = (const float*)d_in[4];
    const float* tmask      = (const float*)d_in[5];
    const float* mix0       = (const float*)d_in[6];
    const float* emb_table  = (const float*)d_in[7];
    const float* W_ih0      = (const float*)d_in[8];
    const float* W_hh0      = (const float*)d_in[9];
    const float* b_ih0      = (const float*)d_in[10];
    const float* b_hh0      = (const float*)d_in[11];
    const float* W_ih1      = (const float*)d_in[12];
    const float* W_hh1      = (const float*)d_in[13];
    const float* b_ih1      = (const float*)d_in[14];
    const float* b_hh1      = (const float*)d_in[15];
    const float* attn_pre_W = (const float*)d_in[16];
    const float* attn_pre_b = (const float*)d_in[17];
    const float* attn_q_W   = (const float*)d_in[18];
    const float* attn_v     = (const float*)d_in[19];
    const float* tattn_pre_W= (const float*)d_in[20];
    const float* tattn_pre_b= (const float*)d_in[21];
    const float* tattn_q_W  = (const float*)d_in[22];
    const float* tattn_v    = (const float*)d_in[23];
    const float* readout_W  = (const float*)d_in[24];
    const float* readout_b  = (const float*)d_in[25];
    const float* gate_W     = (const float*)d_in[26];
    const float* gate_b     = (const float*)d_in[27];
    float* out = (float*)d_out;

    const int T2 = 256;
    auto nb = [](int n){ return (n + 255) / 256; };

    k_init<<<nb(HSZ), T2>>>(hidden);
    k_trans_all<<<5832, T2>>>(W_ih0, W_hh0, W_ih1, W_hh1, readout_W,
                              attn_q_W, tattn_q_W, attn_pre_W, tattn_pre_W,
                              tgt, emb_table);
    k_pre2<<<1300, T2>>>(context, tcontext, attn_pre_b, tattn_pre_b);

    k_persist<<<NBLK, TPB>>>(context, smask, tcontext, tmask, mix0,
                             b_ih0, b_hh0, b_ih1, b_hh1,
                             attn_v, tattn_v, readout_b,
                             gate_W, gate_b, out);
}

// round 14
// speedup vs baseline: 1.2555x; 1.2555x over previous
#include <cuda_runtime.h>
#include <cuda_bf16.h>
#include <cstdint>

#define Bd   64
#define Dd   512
#define Td   50
#define Sd   400
#define KTOP 50
#define NEGV (-1e6f)
#define NBLK 256
#define TPB  256
#define NT   (NBLK*TPB)
#define HSZ  (Bd*Dd)

// ---- output layout ----
#define OFF_G     0
#define SZ_G      (Td*Bd*256)
#define OFF_H     (OFF_G + SZ_G)
#define SZ_H      (2*Bd*Dd)
#define OFF_ATTN  (OFF_H + SZ_H)
#define SZ_ATTN   (Td*Bd*Sd)
#define OFF_TATTN (OFF_ATTN + SZ_ATTN)
#define SZ_TATTN  (Td*Bd*KTOP)
#define OFF_MIX   (OFF_TATTN + SZ_TATTN)
#define OFF_GATE  (OFF_MIX + Bd*Dd)

// ---- scratch ----
__device__ __nv_bfloat16 g_preh [Sd*Bd*Dd];
__device__ __nv_bfloat16 g_tpreh[KTOP*Bd*Dd];
__device__ float g_emb [Td*Bd*Dd];
__device__ float g_embIH[Td*Bd*1536];
__device__ float g_embRO[Td*Bd*512];
__device__ float g_Wt_ih0[1024*1536];
__device__ float g_Wt_hh0[512*1536];
__device__ float g_Wt_ih1[512*1536];
__device__ float g_Wt_hh1[512*1536];
__device__ float g_Wt_ro [1536*512];
__device__ float g_Wt_q  [512*512];
__device__ float g_Wt_tq [512*512];
__device__ float g_Wt_pre[512*512];
__device__ float g_Wt_tpre[512*512];
__device__ float g_h0[HSZ];
__device__ float g_h1[HSZ];
__device__ float g_mix[HSZ];
__device__ float g_xr[Bd*1024];
__device__ float g_gate[Bd];
__device__ float g_e[Bd*(Sd+KTOP)];
__device__ float g_pIH0[8*Bd*1536];
__device__ float g_pHH0[8*Bd*1536];
__device__ float g_pIH1[16*Bd*1536];
__device__ float g_pHH1[16*Bd*1536];
__device__ float g_pQ  [16*Bd*512];
__device__ float g_pTQ [16*Bd*512];
__device__ float g_pRO [16*Bd*512];
// barrier state
__device__ unsigned g_cnt1[16*32];
__device__ unsigned g_cnt2;
__device__ volatile unsigned g_phase;
__device__ unsigned g_bc[64*8];

__device__ __forceinline__ float tanh_fast(float x){
    float y; asm("tanh.approx.f32 %0, %1;" : "=f"(y) : "f"(x)); return y;
}
__device__ __forceinline__ float sigm(float x){ return 1.f/(1.f+__expf(-x)); }

__device__ __forceinline__ float tanh_poly(float x){
    float f = x*x;
    float p = fmaf(f, 0.02186949f, -0.05396825f);
    p = fmaf(f, p, 0.13333333f);
    p = fmaf(f, p, -0.33333333f);
    p = fmaf(f, p, 1.0f);
    return x*p;
}

__device__ __forceinline__ void gsync(unsigned &lp){
    __syncthreads();
    lp++;
    if (threadIdx.x == 0){
        __threadfence();
        int grp = blockIdx.x >> 4;
        if (atomicAdd(&g_cnt1[grp*32], 1u) == 15u){
            g_cnt1[grp*32] = 0;
            if (atomicAdd(&g_cnt2, 1u) == 15u){
                g_cnt2 = 0;
                __threadfence();
                g_phase = lp;
            }
        }
        while (g_phase < lp) { __nanosleep(32); }
        __threadfence();
    }
    __syncthreads();
}

__device__ __forceinline__ float wsum32(float v){
    #pragma unroll
    for (int o = 16; o; o >>= 1) v += __shfl_xor_sync(0xffffffffu, v, o);
    return v;
}
__device__ __forceinline__ float wmax32(float v){
    #pragma unroll
    for (int o = 16; o; o >>= 1) v = fmaxf(v, __shfl_xor_sync(0xffffffffu, v, o));
    return v;
}

// ---- tiled GEMM job, double-buffered smem
__device__ __forceinline__ void gemm_job(
    const float* __restrict__ X, int ldx,
    const float* __restrict__ Wt, int N,
    float* __restrict__ part, int n0, int k0, int kc,
    float (*as)[72], float (*bs)[72])
{
    int tid = threadIdx.x;
    int lr  = tid >> 2, lc4 = (tid & 3) * 4;
    int kkb = tid >> 4, nnb = (tid & 15) * 4;
    int mi0 = (tid >> 4) * 4, ni0 = (tid & 15) * 4;
    float acc[4][4] = {};
    const float* xsrc = X + (size_t)lr*ldx + k0 + lc4;
    const float* wsrc = Wt + (size_t)(k0+kkb)*N + n0 + nnb;
    int nch = kc >> 4;
    float4 xv = *(const float4*)xsrc;
    float4 wv = *(const float4*)wsrc;
    for (int c = 0; c < nch; c++){
        int buf = (c & 1) << 4;
        as[buf+lc4+0][lr] = xv.x; as[buf+lc4+1][lr] = xv.y;
        as[buf+lc4+2][lr] = xv.z; as[buf+lc4+3][lr] = xv.w;
        *(float4*)&bs[buf+kkb][nnb] = wv;
        __syncthreads();
        if (c+1 < nch){
            xv = *(const float4*)(xsrc + (c+1)*16);
            wv = *(const float4*)(wsrc + (size_t)(c+1)*16*N);
        }
        #pragma unroll
        for (int kk = 0; kk < 16; kk++){
            float4 av = *(const float4*)&as[buf+kk][mi0];
            float4 bv = *(const float4*)&bs[buf+kk][ni0];
            float a_[4] = {av.x, av.y, av.z, av.w};
            float b_[4] = {bv.x, bv.y, bv.z, bv.w};
            #pragma unroll
            for (int i = 0; i < 4; i++)
                #pragma unroll
                for (int j = 0; j < 4; j++)
                    acc[i][j] = fmaf(a_[i], b_[j], acc[i][j]);
        }
    }
    __syncthreads();
    #pragma unroll
    for (int i = 0; i < 4; i++){
        *(float4*)(part + (size_t)(mi0+i)*N + n0 + ni0) =
            make_float4(acc[i][0], acc[i][1], acc[i][2], acc[i][3]);
    }
}

struct GemG {
    const float* X; int ldx;
    const float* Wt; int N;
    float* part;
    int kc; int nnt; int njobs;
};

__device__ __forceinline__ void run_gems(const GemG* gs, int ng,
                                         float (*as)[72], float (*bs)[72]){
    int tot = 0;
    for (int g = 0; g < ng; g++) tot += gs[g].njobs;
    for (int j = blockIdx.x; j < tot; j += NBLK){
        int g = 0, base = 0;
        while (j >= base + gs[g].njobs){ base += gs[g].njobs; g++; }
        int local = j - base;
        int nt = local % gs[g].nnt;
        int ks = local / gs[g].nnt;
        gemm_job(gs[g].X, gs[g].ldx, gs[g].Wt, gs[g].N,
                 gs[g].part + (size_t)ks*Bd*gs[g].N,
                 nt*64, ks*gs[g].kc, gs[g].kc, as, bs);
    }
}

// GRU epilogue
__device__ __forceinline__ void gru_epi(
    const float* __restrict__ pIH, int nIH,
    const float* __restrict__ pHH, int nHH,
    const float* __restrict__ embp,
    const float* __restrict__ bih, const float* __restrict__ bhh,
    float* __restrict__ h)
{
    int gtid = blockIdx.x*TPB + threadIdx.x;
    for (int i = gtid; i < HSZ; i += NT){
        int b = i >> 9, d = i & 511;
        float gir = bih[d], giz = bih[512+d], gin = bih[1024+d];
        if (embp){
            const float* e = embp + (size_t)b*1536;
            gir += e[d]; giz += e[512+d]; gin += e[1024+d];
        }
        for (int s = 0; s < nIH; s++){
            const float* p = pIH + (size_t)s*Bd*1536 + (size_t)b*1536;
            gir += p[d]; giz += p[512+d]; gin += p[1024+d];
        }
        float ghr = bhh[d], ghz = bhh[512+d], ghn = bhh[1024+d];
        for (int s = 0; s < nHH; s++){
            const float* p = pHH + (size_t)s*Bd*1536 + (size_t)b*1536;
            ghr += p[d]; ghz += p[512+d]; ghn += p[1024+d];
        }
        float r = sigm(gir + ghr);
        float z = sigm(giz + ghz);
        float n = tanhf(gin + r*ghn);
        h[i] = (1.f - z)*n + z*h[i];
    }
}

__global__ void __launch_bounds__(TPB, 2)
k_persist(const float* __restrict__ context, const float* __restrict__ smask,
          const float* __restrict__ tcontext, const float* __restrict__ tmask,
          const float* __restrict__ mix0,
          const float* __restrict__ b_ih0, const float* __restrict__ b_hh0,
          const float* __restrict__ b_ih1, const float* __restrict__ b_hh1,
          const float* __restrict__ attn_v, const float* __restrict__ tattn_v,
          const float* __restrict__ readout_b,
          const float* __restrict__ gate_W, const float* __restrict__ gate_b,
          float* __restrict__ out)
{
    __shared__ __align__(16) float as[32][72];
    __shared__ __align__(16) float bs[32][72];
    __shared__ float sh[512];
    __shared__ __align__(16) float qsm[512], tqsm[512], vsm[512], tvsm[512];
    const int blk = blockIdx.x;
    const int tid = threadIdx.x;
    const int warp = tid >> 5, lane = tid & 31;
    const int gtid = blk*TPB + tid;
    unsigned lp = g_phase;                 // replay-safe relative base
    const int pb = blk >> 2;
    unsigned bcbase = 0;
    if (tid == 0) bcbase = g_bc[pb*8];

    for (int i = tid; i < 512; i += TPB){ vsm[i] = attn_v[i]; tvsm[i] = tattn_v[i]; }

    // P0: mix = mix0
    for (int i = gtid; i < HSZ; i += NT) g_mix[i] = mix0[i];
    gsync(lp);

    // P1: GRU0(0) gemms
    {
        GemG gs[2] = {
            { g_mix, 512, g_Wt_ih0 + (size_t)512*1536, 1536, g_pIH0, 64, 24, 192 },
            { g_h0,  512, g_Wt_hh0,                    1536, g_pHH0, 64, 24, 192 },
        };
        run_gems(gs, 2, as, bs);
    }
    gsync(lp);

    for (int t = 0; t < Td; t++){
        // epiA: GRU0 epilogue -> h0
        gru_epi(g_pIH0, 8, g_pHH0, 8, g_embIH + (size_t)t*Bd*1536,
                b_ih0, b_hh0, g_h0);
        gsync(lp);

        // gemB: GRU1 gemms
        {
            GemG gs[2] = {
                { g_h0, 512, g_Wt_ih1, 1536, g_pIH1, 32, 24, 384 },
                { g_h1, 512, g_Wt_hh1, 1536, g_pHH1, 32, 24, 384 },
            };
            run_gems(gs, 2, as, bs);
        }
        gsync(lp);

        // epiC: GRU1 epilogue -> h1
        gru_epi(g_pIH1, 16, g_pHH1, 16, nullptr, b_ih1, b_hh1, g_h1);
        gsync(lp);

        // gemD: q + tq gemms + maxout(t-1)
        {
            GemG gs[2] = {
                { g_h1, 512, g_Wt_q,  512, g_pQ,  32, 8, 128 },
                { g_h1, 512, g_Wt_tq, 512, g_pTQ, 32, 8, 128 },
            };
            run_gems(gs, 2, as, bs);
            if (t > 0){
                const float* embro = g_embRO + (size_t)(t-1)*Bd*512;
                for (int i = gtid; i < Bd*256; i += NT){
                    int b = i >> 8, j = i & 255;
                    const float* e = embro + (size_t)b*512;
                    float r0 = readout_b[2*j]   + e[2*j];
                    float r1 = readout_b[2*j+1] + e[2*j+1];
                    #pragma unroll
                    for (int s = 0; s < 16; s++){
                        const float* p = g_pRO + (size_t)s*Bd*512 + (size_t)b*512;
                        r0 += p[2*j]; r1 += p[2*j+1];
                    }
                    out[OFF_G + (size_t)(t-1)*Bd*256 + i] = fmaxf(r0, r1);
                }
            }
        }
        gsync(lp);

        // PDPE: energies (bf16 pre) + per-b mini-barrier + softmax + weighted sums (fp32 ctx)
        {
            int b = pb, q = blk & 3;
            for (int i = tid; i < 128; i += TPB){
                float4 s1 = make_float4(0.f,0.f,0.f,0.f);
                float4 s2 = make_float4(0.f,0.f,0.f,0.f);
                #pragma unroll
                for (int s = 0; s < 16; s++){
                    float4 p1 = *(const float4*)&g_pQ [(size_t)s*HSZ + (size_t)b*512 + i*4];
                    float4 p2 = *(const float4*)&g_pTQ[(size_t)s*HSZ + (size_t)b*512 + i*4];
                    s1.x += p1.x; s1.y += p1.y; s1.z += p1.z; s1.w += p1.w;
                    s2.x += p2.x; s2.y += p2.y; s2.z += p2.z; s2.w += p2.w;
                }
                *(float4*)&qsm[i*4]  = s1;
                *(float4*)&tqsm[i*4] = s2;
            }
            __syncthreads();
            if (q == 0 && warp == 0){
                const float4* h4 = (const float4*)(g_h1 + (size_t)b*512);
                const float4* w4 = (const float4*)gate_W;
                float p = 0.f;
                #pragma unroll
                for (int i = lane; i < 128; i += 32){
                    float4 h = h4[i], w = w4[i];
                    p += h.x*w.x + h.y*w.y + h.z*w.z + h.w*w.w;
                }
                p = wsum32(p);
                if (lane == 0){
                    float g = sigm(p + gate_b[0]);
                    g_gate[b] = g;
                    out[OFF_GATE + (size_t)t*Bd + b] = g;
                }
            }
            int qstart = (450*q) >> 2, qend = (450*(q+1)) >> 2;
            for (int i = qstart + warp; i < qend; i += 8){
                const __nv_bfloat16* prow; const float* qs; const float* vs;
                bool masked; int eidx;
                if (i < Sd){
                    prow = g_preh + ((size_t)i*Bd + b)*512;
                    qs = qsm; vs = vsm;
                    masked = smask[(size_t)b*Sd + i] > 0.5f;
                    eidx = b*(Sd+KTOP) + i;
                } else {
                    int jj = i - Sd;
                    prow = g_tpreh + ((size_t)jj*Bd + b)*512;
                    qs = tqsm; vs = tvsm;
                    masked = tmask[(size_t)b*KTOP + jj] > 0.5f;
                    eidx = b*(Sd+KTOP) + i;
                }
                const uint4* p4 = (const uint4*)prow;     // 8 bf16 per uint4
                float p = 0.f;
                #pragma unroll
                for (int i2 = lane; i2 < 64; i2 += 32){
                    uint4 pk = p4[i2];
                    float2 f0 = __bfloat1622float2(*(__nv_bfloat162*)&pk.x);
                    float2 f1 = __bfloat1622float2(*(__nv_bfloat162*)&pk.y);
                    float2 f2 = __bfloat1622float2(*(__nv_bfloat162*)&pk.z);
                    float2 f3 = __bfloat1622float2(*(__nv_bfloat162*)&pk.w);
                    float4 q0 = *(const float4*)&qs[i2*8];
                    float4 q1 = *(const float4*)&qs[i2*8+4];
                    float4 v0 = *(const float4*)&vs[i2*8];
                    float4 v1 = *(const float4*)&vs[i2*8+4];
                    float x0 = f0.x+q0.x, x1 = f0.y+q0.y;
                    float x2 = f1.x+q0.z, x3 = f1.y+q0.w;
                    float x4 = f2.x+q1.x, x5 = f2.y+q1.y;
                    float x6 = f3.x+q1.z, x7 = f3.y+q1.w;
                    float mx = fmaxf(fmaxf(fmaxf(fabsf(x0),fabsf(x1)),
                                           fmaxf(fabsf(x2),fabsf(x3))),
                                     fmaxf(fmaxf(fabsf(x4),fabsf(x5)),
                                           fmaxf(fabsf(x6),fabsf(x7))));
                    if (__any_sync(0xffffffffu, mx > 0.55f)){
                        p += v0.x*tanh_fast(x0) + v0.y*tanh_fast(x1)
                           + v0.z*tanh_fast(x2) + v0.w*tanh_fast(x3)
                           + v1.x*tanh_fast(x4) + v1.y*tanh_fast(x5)
                           + v1.z*tanh_fast(x6) + v1.w*tanh_fast(x7);
                    } else {
                        p += v0.x*tanh_poly(x0) + v0.y*tanh_poly(x1)
                           + v0.z*tanh_poly(x2) + v0.w*tanh_poly(x3)
                           + v1.x*tanh_poly(x4) + v1.y*tanh_poly(x5)
                           + v1.z*tanh_poly(x6) + v1.w*tanh_poly(x7);
                    }
                }
                p = wsum32(p);
                if (lane == 0) g_e[eidx] = masked ? NEGV : p;
            }
            // per-b mini-barrier (4 blocks)
            __syncthreads();
            if (tid == 0){
                __threadfence();
                atomicAdd(&g_bc[b*8], 1u);
                unsigned target = bcbase + 4u*(unsigned)(t+1);
                while (*((volatile unsigned*)&g_bc[b*8]) < target) { __nanosleep(32); }
                __threadfence();
            }
            __syncthreads();
            // PE
            for (int j = tid; j < Sd+KTOP; j += TPB) qsm[j] = g_e[(size_t)b*(Sd+KTOP) + j];
            __syncthreads();
            float m = -1e30f;
            for (int j = tid; j < Sd; j += TPB) m = fmaxf(m, qsm[j]);
            m = wmax32(m);
            if (lane == 0) sh[warp] = m;
            __syncthreads();
            if (tid == 0){
                float mm = sh[0];
                for (int w = 1; w < 8; w++) mm = fmaxf(mm, sh[w]);
                sh[16] = mm;
            }
            __syncthreads();
            float smax = sh[16];
            float ss = 0.f;
            for (int j = tid; j < Sd; j += TPB){
                float ex = __expf(qsm[j] - smax); qsm[j] = ex; ss += ex;
            }
            ss = wsum32(ss);
            if (lane == 0) sh[warp] = ss;
            __syncthreads();
            if (tid == 0){
                float s = 0.f;
                for (int w = 0; w < 8; w++) s += sh[w];
                sh[17] = 1.f/s;
            }
            __syncthreads();
            float sinv = sh[17];
            if (warp == 0){
                float tm = -1e30f;
                for (int j = lane; j < KTOP; j += 32) tm = fmaxf(tm, qsm[Sd+j]);
                tm = wmax32(tm);
                float te = 0.f;
                for (int j = lane; j < KTOP; j += 32){
                    float ex = __expf(qsm[Sd+j] - tm); qsm[Sd+j] = ex; te += ex;
                }
                te = wsum32(te);
                if (lane == 0) sh[18] = 1.f/te;
            }
            __syncthreads();
            float tinv = sh[18];
            if (q == 0){
                for (int j = tid; j < Sd; j += TPB)
                    out[OFF_ATTN + (size_t)t*Bd*Sd + (size_t)b*Sd + j] = qsm[j]*sinv;
                if (tid < KTOP)
                    out[OFF_TATTN + (size_t)t*Bd*KTOP + (size_t)b*KTOP + tid] = qsm[Sd+tid]*tinv;
            }
            int dl = tid & 127, lh = tid >> 7;
            int d2 = q*128 + dl;
            const float* cb = context + (size_t)b*Dd + d2;
            float a0 = 0.f, a1 = 0.f;
            int l0 = lh*200;
            for (int l = l0; l < l0+200; l += 2){
                a0 += qsm[l]  *cb[(size_t)(l  )*HSZ];
                a1 += qsm[l+1]*cb[(size_t)(l+1)*HSZ];
            }
            tqsm[tid] = a0 + a1;
            const float* tb = tcontext + (size_t)b*Dd + d2;
            float t0 = 0.f;
            int tl0 = lh*25;
            for (int l = tl0; l < tl0+25; l++)
                t0 += qsm[Sd+l]*tb[(size_t)l*HSZ];
            sh[tid] = t0;
            __syncthreads();
            if (tid < 128){
                float c  = (tqsm[tid] + tqsm[tid+128]) * sinv;
                float tc = (sh[tid]   + sh[tid+128])   * tinv;
                float g = g_gate[b];
                float mval = g*c + (1.f - g)*tc;
                g_xr[(size_t)b*1024 + d2]       = g_h1[(size_t)b*Dd + d2];
                g_xr[(size_t)b*1024 + 512 + d2] = mval;
                g_mix[(size_t)b*512 + d2] = mval;
                if (t == Td-1) out[OFF_MIX + (size_t)b*Dd + d2] = mval;
            }
        }
        gsync(lp);

        // gemF: readout + (t<Td-1: GRU0(t+1) gemms)
        if (t < Td-1){
            GemG gs[3] = {
                { g_xr, 1024, g_Wt_ro  + (size_t)512*512,   512, g_pRO,  64,  8, 128 },
                { g_mix, 512, g_Wt_ih0 + (size_t)512*1536, 1536, g_pIH0, 64, 24, 192 },
                { g_h0,  512, g_Wt_hh0,                    1536, g_pHH0, 64, 24, 192 },
            };
            run_gems(gs, 3, as, bs);
        } else {
            GemG gs[1] = {
                { g_xr, 1024, g_Wt_ro + (size_t)512*512, 512, g_pRO, 64, 8, 128 },
            };
            run_gems(gs, 1, as, bs);
        }
        gsync(lp);
    }

    // postlude
    {
        const float* embro = g_embRO + (size_t)(Td-1)*Bd*512;
        for (int i = gtid; i < Bd*256; i += NT){
            int b = i >> 8, j = i & 255;
            const float* e = embro + (size_t)b*512;
            float r0 = readout_b[2*j]   + e[2*j];
            float r1 = readout_b[2*j+1] + e[2*j+1];
            #pragma unroll
            for (int s = 0; s < 16; s++){
                const float* p = g_pRO + (size_t)s*Bd*512 + (size_t)b*512;
                r0 += p[2*j]; r1 += p[2*j+1];
            }
            out[OFF_G + (size_t)(Td-1)*Bd*256 + i] = fmaxf(r0, r1);
        }
    }
    for (int i = gtid; i < HSZ; i += NT){
        out[OFF_H + i]       = g_h0[i];
        out[OFF_H + HSZ + i] = g_h1[i];
    }
}

// ---------------- precompute kernels ----------------

// transposes + embedding gather
__global__ void k_trans_all(const float* __restrict__ W_ih0, const float* __restrict__ W_hh0,
                            const float* __restrict__ W_ih1, const float* __restrict__ W_hh1,
                            const float* __restrict__ readout_W,
                            const float* __restrict__ attn_q_W, const float* __restrict__ tattn_q_W,
                            const float* __restrict__ attn_pre_W, const float* __restrict__ tattn_pre_W,
                            const int* __restrict__ tgt, const float* __restrict__ table){
    __shared__ float tile[32][33];
    int bid = blockIdx.x;
    int tid = threadIdx.x;
    if (bid >= 5632){
        int r0 = (bid - 5632) * 16;
        for (int e = tid; e < 16*512; e += 256){
            int row = r0 + (e >> 9), d = e & 511;
            int tok = tgt[row];
            g_emb[(size_t)row*512 + d] = table[(size_t)tok*512 + d];
        }
        return;
    }
    const float* src; float* dst; int R, C, t0;
    if      (bid < 1536){ src=W_ih0;       dst=g_Wt_ih0;  R=1536; C=1024; t0=0; }
    else if (bid < 2304){ src=W_hh0;       dst=g_Wt_hh0;  R=1536; C=512;  t0=1536; }
    else if (bid < 3072){ src=W_ih1;       dst=g_Wt_ih1;  R=1536; C=512;  t0=2304; }
    else if (bid < 3840){ src=W_hh1;       dst=g_Wt_hh1;  R=1536; C=512;  t0=3072; }
    else if (bid < 4608){ src=readout_W;   dst=g_Wt_ro;   R=512;  C=1536; t0=3840; }
    else if (bid < 4864){ src=attn_q_W;    dst=g_Wt_q;    R=512;  C=512;  t0=4608; }
    else if (bid < 5120){ src=tattn_q_W;   dst=g_Wt_tq;   R=512;  C=512;  t0=4864; }
    else if (bid < 5376){ src=attn_pre_W;  dst=g_Wt_pre;  R=512;  C=512;  t0=5120; }
    else                { src=tattn_pre_W; dst=g_Wt_tpre; R=512;  C=512;  t0=5376; }
    int lt = bid - t0;
    int ctiles = C >> 5;
    int tr = lt / ctiles, tc = lt % ctiles;
    int r0 = tr << 5, c0 = tc << 5;
    int ty = tid >> 5, tx = tid & 31;
    for (int rr = ty; rr < 32; rr += 8)
        tile[rr][tx] = src[(size_t)(r0+rr)*C + c0 + tx];
    __syncthreads();
    for (int rr = ty; rr < 32; rr += 8)
        dst[(size_t)(c0+rr)*R + r0 + tx] = tile[tx][rr];
}

__global__ void k_init(const float* __restrict__ hidden){
    int i = blockIdx.x*blockDim.x + threadIdx.x;
    if (i == 0){ g_cnt2 = 0; g_phase = 0; }
    if (i < 16*32) g_cnt1[i] = 0;
    if (i < 64*8) g_bc[i] = 0;
    if (i < HSZ){
        g_h0[i] = hidden[i];
        g_h1[i] = hidden[HSZ + i];
    }
}

// precompute GEMM, 128x128 tiles, 8x8 micro; pre/tpre written as bf16
__global__ void k_pre2(const float* __restrict__ context, const float* __restrict__ tcontext,
                       const float* __restrict__ attn_pre_b, const float* __restrict__ tattn_pre_b){
    int bid = blockIdx.x;
    const float *X, *Wt, *bias; void* Cv; int N, base; bool tob16;
    if      (bid < 800) { X=context;  Wt=g_Wt_pre;  bias=attn_pre_b;  Cv=g_preh;  N=512;  base=0;   tob16=true; }
    else if (bid < 900) { X=tcontext; Wt=g_Wt_tpre; bias=tattn_pre_b; Cv=g_tpreh; N=512;  base=800; tob16=true; }
    else if (bid < 1200){ X=g_emb;    Wt=g_Wt_ih0;  bias=nullptr;     Cv=g_embIH; N=1536; base=900; tob16=false; }
    else                { X=g_emb;    Wt=g_Wt_ro;   bias=nullptr;     Cv=g_embRO; N=512;  base=1200; tob16=false; }
    int lb = bid - base;
    int ntiles = N >> 7;
    const int m0 = (lb / ntiles) * 128;
    const int n0 = (lb % ntiles) * 128;
    __shared__ __align__(16) float ash[16][132];
    __shared__ __align__(16) float bsh[16][136];
    int tid = threadIdx.x;
    int mi0 = (tid >> 4) * 8;
    int ni0 = (tid & 15) * 8;
    float acc[8][8] = {};
    int lr = tid >> 2, lc = (tid & 3) * 4;
    int kb = tid >> 5, nb4 = (tid & 31) * 4;
    for (int k0 = 0; k0 < 512; k0 += 16){
        #pragma unroll
        for (int h = 0; h < 2; h++){
            int row = lr + h*64;
            float4 xv = *(const float4*)(X + (size_t)(m0+row)*512 + k0 + lc);
            ash[lc+0][row] = xv.x; ash[lc+1][row] = xv.y;
            ash[lc+2][row] = xv.z; ash[lc+3][row] = xv.w;
        }
        #pragma unroll
        for (int h = 0; h < 2; h++){
            int kk = kb + h*8;
            *(float4*)&bsh[kk][nb4] = *(const float4*)(Wt + (size_t)(k0+kk)*N + n0 + nb4);
        }
        __syncthreads();
        #pragma unroll
        for (int kk = 0; kk < 16; kk++){
            float a_[8], b_[8];
            float4 a0 = *(const float4*)&ash[kk][mi0];
            float4 a1 = *(const float4*)&ash[kk][mi0+4];
            float4 b0 = *(const float4*)&bsh[kk][ni0];
            float4 b1 = *(const float4*)&bsh[kk][ni0+4];
            a_[0]=a0.x;a_[1]=a0.y;a_[2]=a0.z;a_[3]=a0.w;
            a_[4]=a1.x;a_[5]=a1.y;a_[6]=a1.z;a_[7]=a1.w;
            b_[0]=b0.x;b_[1]=b0.y;b_[2]=b0.z;b_[3]=b0.w;
            b_[4]=b1.x;b_[5]=b1.y;b_[6]=b1.z;b_[7]=b1.w;
            #pragma unroll
            for (int i = 0; i < 8; i++)
                #pragma unroll
                for (int j = 0; j < 8; j++)
                    acc[i][j] = fmaf(a_[i], b_[j], acc[i][j]);
        }
        __syncthreads();
    }
    #pragma unroll
    for (int i = 0; i < 8; i++){
        if (tob16){
            __nv_bfloat16* cp = (__nv_bfloat16*)Cv + (size_t)(m0+mi0+i)*N + n0 + ni0;
            #pragma unroll
            for (int j = 0; j < 8; j++)
                cp[j] = __float2bfloat16(acc[i][j] + (bias ? bias[n0+ni0+j] : 0.f));
        } else {
            float* cp = (float*)Cv + (size_t)(m0+mi0+i)*N + n0 + ni0;
            #pragma unroll
            for (int j = 0; j < 8; j++)
                cp[j] = acc[i][j] + (bias ? bias[n0+ni0+j] : 0.f);
        }
    }
}

// ---------------- host ----------------

extern "C" void kernel_launch(void* const* d_in, const int* in_sizes, int n_in,
                              void* d_out, int out_size){
    const int*   tgt        = (const int*)  d_in[0];
    const float* hidden     = (const float*)d_in[1];
    const float* context    = (const float*)d_in[2];
    const float* smask      = (const float*)d_in[3];
    const float* tcontext   = (const float*)d_in[4];
    const float* tmask      = (const float*)d_in[5];
    const float* mix0       = (const float*)d_in[6];
    const float* emb_table  = (const float*)d_in[7];
    const float* W_ih0      = (const float*)d_in[8];
    const float* W_hh0      = (const float*)d_in[9];
    const float* b_ih0      = (const float*)d_in[10];
    const float* b_hh0      = (const float*)d_in[11];
    const float* W_ih1      = (const float*)d_in[12];
    const float* W_hh1      = (const float*)d_in[13];
    const float* b_ih1      = (const float*)d_in[14];
    const float* b_hh1      = (const float*)d_in[15];
    const float* attn_pre_W = (const float*)d_in[16];
    const float* attn_pre_b = (const float*)d_in[17];
    const float* attn_q_W   = (const float*)d_in[18];
    const float* attn_v     = (const float*)d_in[19];
    const float* tattn_pre_W= (const float*)d_in[20];
    const float* tattn_pre_b= (const float*)d_in[21];
    const float* tattn_q_W  = (const float*)d_in[22];
    const float* tattn_v    = (const float*)d_in[23];
    const float* readout_W  = (const float*)d_in[24];
    const float* readout_b  = (const float*)d_in[25];
    const float* gate_W     = (const float*)d_in[26];
    const float* gate_b     = (const float*)d_in[27];
    float* out = (float*)d_out;

    const int T2 = 256;
    auto nb = [](int n){ return (n + 255) / 256; };

    k_init<<<nb(HSZ), T2>>>(hidden);
    k_trans_all<<<5832, T2>>>(W_ih0, W_hh0, W_ih1, W_hh1, readout_W,
                              attn_q_W, tattn_q_W, attn_pre_W, tattn_pre_W,
                              tgt, emb_table);
    k_pre2<<<1300, T2>>>(context, tcontext, attn_pre_b, tattn_pre_b);

    k_persist<<<NBLK, TPB>>>(context, smask, tcontext, tmask, mix0,
                             b_ih0, b_hh0, b_ih1, b_hh1,
                             attn_v, tattn_v, readout_b,
                             gate_W, gate_b, out);
}